// round 1
// baseline (speedup 1.0000x reference)
#include <cuda_runtime.h>

#define N_NODES 100000
#define KK 5
#define CC 16
#define EE 3200000

// Scratch: Z transposed to [K][N] so each k's gather slice is contiguous (400 KB, L2-resident).
__device__ float g_Zt[KK * N_NODES];

// Kernel 1: Z = X @ h  (stored k-major), and zero the output (d_out is poisoned).
__global__ __launch_bounds__(256) void compute_z_kernel(
    const float* __restrict__ X,
    const float* __restrict__ h,
    float* __restrict__ y)
{
    __shared__ float hs[CC * KK];
    if (threadIdx.x < CC * KK) hs[threadIdx.x] = h[threadIdx.x];
    __syncthreads();

    int n = blockIdx.x * blockDim.x + threadIdx.x;
    if (n >= N_NODES) return;

    float x[CC];
    const float4* xp = reinterpret_cast<const float4*>(X + (size_t)n * CC);
#pragma unroll
    for (int i = 0; i < CC / 4; i++) {
        float4 v = xp[i];
        x[4 * i + 0] = v.x;
        x[4 * i + 1] = v.y;
        x[4 * i + 2] = v.z;
        x[4 * i + 3] = v.w;
    }

#pragma unroll
    for (int k = 0; k < KK; k++) {
        float acc = 0.f;
#pragma unroll
        for (int c = 0; c < CC; c++) acc += x[c] * hs[c * KK + k];
        g_Zt[k * N_NODES + n] = acc;
    }
    y[n] = 0.f;
}

// Kernel 2: for each edge (k,e): y[rows] += vals * Zt[k][cols].
// Vectorized by 4; E % 4 == 0 so a 4-pack never crosses a k boundary.
__global__ __launch_bounds__(256) void scatter_kernel(
    const int4*   __restrict__ rows,
    const int4*   __restrict__ cols,
    const float4* __restrict__ vals,
    float* __restrict__ y)
{
    int i = blockIdx.x * blockDim.x + threadIdx.x;   // i in [0, K*E/4) = [0, 4M)
    int k = (i * 4) / EE;                            // constant within the pack
    const float* __restrict__ Z = g_Zt + k * N_NODES;

    int4   r = rows[i];
    int4   c = cols[i];
    float4 v = vals[i];

    float z0 = __ldg(&Z[c.x]);
    float z1 = __ldg(&Z[c.y]);
    float z2 = __ldg(&Z[c.z]);
    float z3 = __ldg(&Z[c.w]);

    atomicAdd(&y[r.x], v.x * z0);
    atomicAdd(&y[r.y], v.y * z1);
    atomicAdd(&y[r.z], v.z * z2);
    atomicAdd(&y[r.w], v.w * z3);
}

extern "C" void kernel_launch(void* const* d_in, const int* in_sizes, int n_in,
                              void* d_out, int out_size) {
    const float* X    = (const float*)d_in[0];
    const int*   rows = (const int*)d_in[1];
    const int*   cols = (const int*)d_in[2];
    const float* vals = (const float*)d_in[3];
    const float* h    = (const float*)d_in[4];
    float* y = (float*)d_out;

    // Kernel 1: Z + zero y
    {
        int threads = 256;
        int blocks = (N_NODES + threads - 1) / threads;
        compute_z_kernel<<<blocks, threads>>>(X, h, y);
    }

    // Kernel 2: gather + scatter over 16M edges, 4 per thread
    {
        int total4 = KK * EE / 4;        // 4,000,000
        int threads = 256;
        int blocks = total4 / threads;   // 15625, exact
        scatter_kernel<<<blocks, threads>>>(
            (const int4*)rows, (const int4*)cols, (const float4*)vals, y);
    }
}

// round 2
// speedup vs baseline: 1.3851x; 1.3851x over previous
#include <cuda_runtime.h>
#include <cuda_fp16.h>

#define N_NODES 100000
#define KK 5
#define CC 16
#define EE 3200000
#define PACKS_PER_K (EE / 4)          // 800000 int4-packs per k
#define PACKS_PER_THREAD 2            // 8 edges per thread

// Z transposed, fp16: each k-slice is 200 KB -> fits in L1D (228 KB).
__device__ __half g_Zt[KK * N_NODES];

// Kernel 1: Z = X @ h (k-major, fp16), and zero y (d_out is poisoned).
__global__ __launch_bounds__(256) void compute_z_kernel(
    const float* __restrict__ X,
    const float* __restrict__ h,
    float* __restrict__ y)
{
    __shared__ float hs[CC * KK];
    if (threadIdx.x < CC * KK) hs[threadIdx.x] = h[threadIdx.x];
    __syncthreads();

    int n = blockIdx.x * blockDim.x + threadIdx.x;
    if (n >= N_NODES) return;

    float x[CC];
    const float4* xp = reinterpret_cast<const float4*>(X + (size_t)n * CC);
#pragma unroll
    for (int i = 0; i < CC / 4; i++) {
        float4 v = xp[i];
        x[4 * i + 0] = v.x;
        x[4 * i + 1] = v.y;
        x[4 * i + 2] = v.z;
        x[4 * i + 3] = v.w;
    }

#pragma unroll
    for (int k = 0; k < KK; k++) {
        float acc = 0.f;
#pragma unroll
        for (int c = 0; c < CC; c++) acc += x[c] * hs[c * KK + k];
        g_Zt[k * N_NODES + n] = __float2half_rn(acc);
    }
    y[n] = 0.f;
}

// Kernel 2: y[rows] += vals * Zt[k][cols], 8 edges per thread.
// grid = (ceil(PACKS_PER_K/(256*2)), KK); blockIdx.y = k.
// Streams bypass L1 (__ldcg) so L1D holds only the 200 KB fp16 Z slice.
__global__ __launch_bounds__(256) void scatter_kernel(
    const int4*   __restrict__ rows,
    const int4*   __restrict__ cols,
    const float4* __restrict__ vals,
    float* __restrict__ y)
{
    const int k = blockIdx.y;
    const __half* __restrict__ Z = g_Zt + k * N_NODES;

    int t = blockIdx.x * blockDim.x + threadIdx.x;   // pack-pair index within k
    int p0 = 2 * t;
    if (p0 >= PACKS_PER_K) return;
    int i0 = k * PACKS_PER_K + p0;
    int i1 = i0 + 1;                                  // p0+1 < PACKS_PER_K (PACKS_PER_K even)

    // Stream loads (L2-only)
    int4   r0 = __ldcg(rows + i0);
    int4   c0 = __ldcg(cols + i0);
    float4 v0 = __ldcg(vals + i0);
    int4   r1 = __ldcg(rows + i1);
    int4   c1 = __ldcg(cols + i1);
    float4 v1 = __ldcg(vals + i1);

    // 8 gathers from the L1-resident fp16 slice (issued back-to-back for MLP)
    float z0 = __half2float(__ldg(Z + c0.x));
    float z1 = __half2float(__ldg(Z + c0.y));
    float z2 = __half2float(__ldg(Z + c0.z));
    float z3 = __half2float(__ldg(Z + c0.w));
    float z4 = __half2float(__ldg(Z + c1.x));
    float z5 = __half2float(__ldg(Z + c1.y));
    float z6 = __half2float(__ldg(Z + c1.z));
    float z7 = __half2float(__ldg(Z + c1.w));

    // 8 reductions (return value unused -> REDG)
    atomicAdd(&y[r0.x], v0.x * z0);
    atomicAdd(&y[r0.y], v0.y * z1);
    atomicAdd(&y[r0.z], v0.z * z2);
    atomicAdd(&y[r0.w], v0.w * z3);
    atomicAdd(&y[r1.x], v1.x * z4);
    atomicAdd(&y[r1.y], v1.y * z5);
    atomicAdd(&y[r1.z], v1.z * z6);
    atomicAdd(&y[r1.w], v1.w * z7);
}

extern "C" void kernel_launch(void* const* d_in, const int* in_sizes, int n_in,
                              void* d_out, int out_size) {
    const float* X    = (const float*)d_in[0];
    const int*   rows = (const int*)d_in[1];
    const int*   cols = (const int*)d_in[2];
    const float* vals = (const float*)d_in[3];
    const float* h    = (const float*)d_in[4];
    float* y = (float*)d_out;

    {
        int threads = 256;
        int blocks = (N_NODES + threads - 1) / threads;
        compute_z_kernel<<<blocks, threads>>>(X, h, y);
    }
    {
        dim3 block(256);
        dim3 grid((PACKS_PER_K / PACKS_PER_THREAD + 255) / 256, KK);  // (1563, 5)
        scatter_kernel<<<grid, block>>>(
            (const int4*)rows, (const int4*)cols, (const float4*)vals, y);
    }
}

// round 3
// speedup vs baseline: 1.4044x; 1.0140x over previous
#include <cuda_runtime.h>
#include <cuda_fp16.h>

#define N_NODES 100000
#define KK 5
#define CC 16
#define EE 3200000
#define PACKS_PER_KSEG (EE / 4)           // 800,000 int4-packs per k
#define PACKS_TOTAL (KK * PACKS_PER_KSEG) // 4,000,000
#define NTHREADS 1024
#define SLICE_BYTES (N_NODES * 2)         // 200,000 B fp16 slice
#define SLICE_INT4 (SLICE_BYTES / 16)     // 12,500

// Z transposed, fp16, k-major.
__device__ __half g_Zt[KK * N_NODES];

// Kernel 1: Z = X @ h (k-major, fp16), and zero y (d_out is poisoned).
__global__ __launch_bounds__(256) void compute_z_kernel(
    const float* __restrict__ X,
    const float* __restrict__ h,
    float* __restrict__ y)
{
    __shared__ float hs[CC * KK];
    if (threadIdx.x < CC * KK) hs[threadIdx.x] = h[threadIdx.x];
    __syncthreads();

    int n = blockIdx.x * blockDim.x + threadIdx.x;
    if (n >= N_NODES) return;

    float x[CC];
    const float4* xp = reinterpret_cast<const float4*>(X + (size_t)n * CC);
#pragma unroll
    for (int i = 0; i < CC / 4; i++) {
        float4 v = xp[i];
        x[4 * i + 0] = v.x;
        x[4 * i + 1] = v.y;
        x[4 * i + 2] = v.z;
        x[4 * i + 3] = v.w;
    }

#pragma unroll
    for (int k = 0; k < KK; k++) {
        float acc = 0.f;
#pragma unroll
        for (int c = 0; c < CC; c++) acc += x[c] * hs[c * KK + k];
        g_Zt[k * N_NODES + n] = __float2half_rn(acc);
    }
    y[n] = 0.f;
}

// Kernel 2: per-CTA contiguous pack range; the active k-slice lives in SMEM
// (200 KB), so each gather is an LDS.U16 (crossbar, ~N-conflict cycles per
// warp) instead of an L1tex wavefront per lane. Atomics (REDG) are the floor.
__global__ __launch_bounds__(NTHREADS, 1) void scatter_kernel(
    const int4*   __restrict__ rows,
    const int4*   __restrict__ cols,
    const float4* __restrict__ vals,
    float* __restrict__ y)
{
    extern __shared__ __align__(16) __half sZ[];
    const int tid = threadIdx.x;

    // Contiguous pack range for this CTA.
    long long bid  = blockIdx.x;
    long long nb   = gridDim.x;
    int p   = (int)((bid * PACKS_TOTAL) / nb);
    int end = (int)(((bid + 1) * PACKS_TOTAL) / nb);

    while (p < end) {
        int k    = p / PACKS_PER_KSEG;
        int kend = (k + 1) * PACKS_PER_KSEG;
        if (kend > end) kend = end;

        // Stage slice k into smem (sync first: prior segment's readers).
        __syncthreads();
        {
            const int4* src = reinterpret_cast<const int4*>(g_Zt + (size_t)k * N_NODES);
            int4* dst = reinterpret_cast<int4*>(sZ);
            for (int i = tid; i < SLICE_INT4; i += NTHREADS)
                dst[i] = src[i];
        }
        __syncthreads();

        for (int q = p + tid; q < kend; q += NTHREADS) {
            int4   r = __ldcg(rows + q);
            int4   c = __ldcg(cols + q);
            float4 v = __ldcg(vals + q);

            float z0 = __half2float(sZ[c.x]);
            float z1 = __half2float(sZ[c.y]);
            float z2 = __half2float(sZ[c.z]);
            float z3 = __half2float(sZ[c.w]);

            atomicAdd(&y[r.x], v.x * z0);
            atomicAdd(&y[r.y], v.y * z1);
            atomicAdd(&y[r.z], v.z * z2);
            atomicAdd(&y[r.w], v.w * z3);
        }
        p = kend;
    }
}

extern "C" void kernel_launch(void* const* d_in, const int* in_sizes, int n_in,
                              void* d_out, int out_size) {
    const float* X    = (const float*)d_in[0];
    const int*   rows = (const int*)d_in[1];
    const int*   cols = (const int*)d_in[2];
    const float* vals = (const float*)d_in[3];
    const float* h    = (const float*)d_in[4];
    float* y = (float*)d_out;

    {
        int threads = 256;
        int blocks = (N_NODES + threads - 1) / threads;
        compute_z_kernel<<<blocks, threads>>>(X, h, y);
    }
    {
        static int sms = 0;
        if (sms == 0) {
            cudaDeviceGetAttribute(&sms, cudaDevAttrMultiProcessorCount, 0);
            if (sms <= 0) sms = 148;
            cudaFuncSetAttribute(scatter_kernel,
                                 cudaFuncAttributeMaxDynamicSharedMemorySize,
                                 SLICE_BYTES);
        }
        scatter_kernel<<<sms, NTHREADS, SLICE_BYTES>>>(
            (const int4*)rows, (const int4*)cols, (const float4*)vals, y);
    }
}